// round 11
// baseline (speedup 1.0000x reference)
#include <cuda_runtime.h>
#include <math.h>

#define N_TOK 8192
#define C_DIM 1024
#define D_DIM 1024
#define E_NUM 8
#define SLOTS (N_TOK * 2)

#define BM 128
#define BN 128
#define BK 16
#define KTOT 1024
#define NCHUNK (KTOT / BK)   // 64
#define ADS 130              // A-dup smem row stride (b64 elems)

// ---------------- device scratch ----------------
__device__ int   g_counts[E_NUM];
__device__ int   g_base[E_NUM];
__device__ int   g_cursor[E_NUM];
__device__ int   g_tok_e[SLOTS];
__device__ float g_tok_p[SLOTS];
__device__ int   g_slot_tok[SLOTS];
__device__ float g_slot_p[SLOTS];
__device__ float g_hidden[(size_t)(SLOTS + BM) * D_DIM]; // padded

// ---------------- helpers ----------------
__device__ __forceinline__ unsigned long long pk2(float v) {
    unsigned int u = __float_as_uint(v);
    return ((unsigned long long)u << 32) | u;
}
__device__ __forceinline__ void ffma2(unsigned long long& d,
                                      unsigned long long a,
                                      unsigned long long b) {
    asm volatile("fma.rn.f32x2 %0, %1, %2, %0;" : "+l"(d) : "l"(a), "l"(b));
}
__device__ __forceinline__ float lo32(unsigned long long v) {
    return __uint_as_float((unsigned int)v);
}
__device__ __forceinline__ float hi32(unsigned long long v) {
    return __uint_as_float((unsigned int)(v >> 32));
}

// ---------------- small kernels (round-1 proven, byte-identical) ----------------
__global__ void init_kernel() {
    int t = threadIdx.x;
    if (t < E_NUM) g_counts[t] = 0;
}

__global__ void router_kernel(const float* __restrict__ x,
                              const float* __restrict__ rw) {
    __shared__ float srw[E_NUM * C_DIM];
    int tid = threadIdx.x;
    for (int i = tid; i < E_NUM * C_DIM; i += 256) srw[i] = rw[i];
    __syncthreads();

    int warp = tid >> 5, lane = tid & 31;
    int token = blockIdx.x * 8 + warp;
    const float* xr = x + (size_t)token * C_DIM;

    float acc[E_NUM];
#pragma unroll
    for (int e = 0; e < E_NUM; e++) acc[e] = 0.f;
    for (int c = lane; c < C_DIM; c += 32) {
        float xv = xr[c];
#pragma unroll
        for (int e = 0; e < E_NUM; e++) acc[e] += xv * srw[e * C_DIM + c];
    }
#pragma unroll
    for (int e = 0; e < E_NUM; e++) {
#pragma unroll
        for (int o = 16; o; o >>= 1)
            acc[e] += __shfl_xor_sync(0xffffffffu, acc[e], o);
    }
    if (lane == 0) {
        int e0 = 0; float v0 = acc[0];
#pragma unroll
        for (int e = 1; e < E_NUM; e++)
            if (acc[e] > v0) { v0 = acc[e]; e0 = e; }
        int e1 = -1; float v1 = -INFINITY;
#pragma unroll
        for (int e = 0; e < E_NUM; e++)
            if (e != e0 && acc[e] > v1) { v1 = acc[e]; e1 = e; }
        float t  = expf(v1 - v0);
        float p0 = 1.f / (1.f + t);
        float p1 = t / (1.f + t);
        g_tok_e[token * 2 + 0] = e0;
        g_tok_e[token * 2 + 1] = e1;
        g_tok_p[token * 2 + 0] = p0;
        g_tok_p[token * 2 + 1] = p1;
        atomicAdd(&g_counts[e0], 1);
        atomicAdd(&g_counts[e1], 1);
    }
}

__global__ void offsets_kernel() {
    int s = 0;
    for (int e = 0; e < E_NUM; e++) {
        g_base[e]   = s;
        g_cursor[e] = s;
        s += g_counts[e];
    }
}

__global__ void scatter_kernel() {
    int n = blockIdx.x * blockDim.x + threadIdx.x;
    if (n >= N_TOK) return;
#pragma unroll
    for (int k = 0; k < 2; k++) {
        int e = g_tok_e[n * 2 + k];
        int slot = atomicAdd(&g_cursor[e], 1);
        g_slot_tok[slot] = n;
        g_slot_p[slot]   = g_tok_p[n * 2 + k];
    }
}

// ---------------- GEMM1: H = relu(x[tok] @ w1[e])^2  (FFMA2, non-template) ----------------
__global__ void __launch_bounds__(256)
gemm1_kernel(const float* __restrict__ x, const float* __restrict__ w1) {
    const int e  = blockIdx.z;
    const int ne = g_counts[e];
    const int m0 = blockIdx.y * BM;
    if (m0 >= ne) return;
    const int base = g_base[e];
    const int n0   = blockIdx.x * BN;

    __shared__ __align__(16) unsigned long long Ad[BK][ADS]; // Ad[k][m] = (a,a)
    __shared__ __align__(16) float Bs[BK][136];
    __shared__ int stok[BM];

    const int t = threadIdx.x;
    if (t < BM) {
        int m = m0 + t;
        stok[t] = (m < ne) ? g_slot_tok[base + m] : 0;
    }
    __syncthreads();

    const int ar   = t >> 1;
    const int aoff = (t & 1) * 8;
    const int brow = t >> 4;
    const int bcol = (t & 15) * 8;

    const float* agp = x + (size_t)stok[ar] * KTOT + aoff;
    const float* bgp = w1 + ((size_t)e << 20) + (size_t)brow * KTOT + n0 + bcol;

    const int tx = t & 15, ty = t >> 4;

    unsigned long long acc[8][4];
#pragma unroll
    for (int i = 0; i < 8; i++)
#pragma unroll
        for (int j = 0; j < 4; j++) acc[i][j] = 0ull;

    for (int c = 0; c < NCHUNK; c++) {
        float4 va0 = *(const float4*)(agp + c * BK);
        float4 va1 = *(const float4*)(agp + c * BK + 4);
        float4 vb0 = *(const float4*)(bgp + (size_t)c * BK * KTOT);
        float4 vb1 = *(const float4*)(bgp + (size_t)c * BK * KTOT + 4);
        __syncthreads();
        Ad[aoff + 0][ar] = pk2(va0.x);
        Ad[aoff + 1][ar] = pk2(va0.y);
        Ad[aoff + 2][ar] = pk2(va0.z);
        Ad[aoff + 3][ar] = pk2(va0.w);
        Ad[aoff + 4][ar] = pk2(va1.x);
        Ad[aoff + 5][ar] = pk2(va1.y);
        Ad[aoff + 6][ar] = pk2(va1.z);
        Ad[aoff + 7][ar] = pk2(va1.w);
        *(float4*)&Bs[brow][bcol]     = vb0;
        *(float4*)&Bs[brow][bcol + 4] = vb1;
        __syncthreads();

#pragma unroll
        for (int kk = 0; kk < BK; kk++) {
            ulonglong2 a01 = *(const ulonglong2*)&Ad[kk][ty * 8];
            ulonglong2 a23 = *(const ulonglong2*)&Ad[kk][ty * 8 + 2];
            ulonglong2 a45 = *(const ulonglong2*)&Ad[kk][ty * 8 + 4];
            ulonglong2 a67 = *(const ulonglong2*)&Ad[kk][ty * 8 + 6];
            ulonglong2 b01 = *(const ulonglong2*)&Bs[kk][tx * 8];
            ulonglong2 b23 = *(const ulonglong2*)&Bs[kk][tx * 8 + 4];
            unsigned long long a2[8] = {a01.x, a01.y, a23.x, a23.y,
                                        a45.x, a45.y, a67.x, a67.y};
            unsigned long long b2[4] = {b01.x, b01.y, b23.x, b23.y};
#pragma unroll
            for (int i = 0; i < 8; i++)
#pragma unroll
                for (int j = 0; j < 4; j++)
                    ffma2(acc[i][j], a2[i], b2[j]);
        }
    }

#pragma unroll
    for (int i = 0; i < 8; i++) {
        int m = m0 + ty * 8 + i;
        if (m >= ne) break;
        float* hp = g_hidden + (size_t)(base + m) * KTOT + n0 + tx * 8;
        float4 o0, o1;
        float r;
        r = fmaxf(lo32(acc[i][0]), 0.f); o0.x = r * r;
        r = fmaxf(hi32(acc[i][0]), 0.f); o0.y = r * r;
        r = fmaxf(lo32(acc[i][1]), 0.f); o0.z = r * r;
        r = fmaxf(hi32(acc[i][1]), 0.f); o0.w = r * r;
        r = fmaxf(lo32(acc[i][2]), 0.f); o1.x = r * r;
        r = fmaxf(hi32(acc[i][2]), 0.f); o1.y = r * r;
        r = fmaxf(lo32(acc[i][3]), 0.f); o1.z = r * r;
        r = fmaxf(hi32(acc[i][3]), 0.f); o1.w = r * r;
        *(float4*)(hp)     = o0;
        *(float4*)(hp + 4) = o1;
    }
}

// ---------------- GEMM2: out[tok] += p * (H @ w2[e])  (FFMA2, non-template) ----------------
__global__ void __launch_bounds__(256)
gemm2_kernel(const float* __restrict__ w2, float* __restrict__ out) {
    const int e  = blockIdx.z;
    const int ne = g_counts[e];
    const int m0 = blockIdx.y * BM;
    if (m0 >= ne) return;
    const int base = g_base[e];
    const int n0   = blockIdx.x * BN;

    __shared__ __align__(16) unsigned long long Ad[BK][ADS];
    __shared__ __align__(16) float Bs[BK][136];
    __shared__ int   stok[BM];
    __shared__ float sp[BM];

    const int t = threadIdx.x;
    if (t < BM) {
        int m = m0 + t;
        if (m < ne) {
            stok[t] = g_slot_tok[base + m];
            sp[t]   = g_slot_p[base + m];
        } else {
            stok[t] = 0;
            sp[t]   = 0.f;
        }
    }
    __syncthreads();

    const int ar   = t >> 1;
    const int aoff = (t & 1) * 8;
    const int brow = t >> 4;
    const int bcol = (t & 15) * 8;

    const float* agp = g_hidden + (size_t)(base + m0 + ar) * KTOT + aoff;
    const float* bgp = w2 + ((size_t)e << 20) + (size_t)brow * KTOT + n0 + bcol;

    const int tx = t & 15, ty = t >> 4;

    unsigned long long acc[8][4];
#pragma unroll
    for (int i = 0; i < 8; i++)
#pragma unroll
        for (int j = 0; j < 4; j++) acc[i][j] = 0ull;

    for (int c = 0; c < NCHUNK; c++) {
        float4 va0 = *(const float4*)(agp + c * BK);
        float4 va1 = *(const float4*)(agp + c * BK + 4);
        float4 vb0 = *(const float4*)(bgp + (size_t)c * BK * KTOT);
        float4 vb1 = *(const float4*)(bgp + (size_t)c * BK * KTOT + 4);
        __syncthreads();
        Ad[aoff + 0][ar] = pk2(va0.x);
        Ad[aoff + 1][ar] = pk2(va0.y);
        Ad[aoff + 2][ar] = pk2(va0.z);
        Ad[aoff + 3][ar] = pk2(va0.w);
        Ad[aoff + 4][ar] = pk2(va1.x);
        Ad[aoff + 5][ar] = pk2(va1.y);
        Ad[aoff + 6][ar] = pk2(va1.z);
        Ad[aoff + 7][ar] = pk2(va1.w);
        *(float4*)&Bs[brow][bcol]     = vb0;
        *(float4*)&Bs[brow][bcol + 4] = vb1;
        __syncthreads();

#pragma unroll
        for (int kk = 0; kk < BK; kk++) {
            ulonglong2 a01 = *(const ulonglong2*)&Ad[kk][ty * 8];
            ulonglong2 a23 = *(const ulonglong2*)&Ad[kk][ty * 8 + 2];
            ulonglong2 a45 = *(const ulonglong2*)&Ad[kk][ty * 8 + 4];
            ulonglong2 a67 = *(const ulonglong2*)&Ad[kk][ty * 8 + 6];
            ulonglong2 b01 = *(const ulonglong2*)&Bs[kk][tx * 8];
            ulonglong2 b23 = *(const ulonglong2*)&Bs[kk][tx * 8 + 4];
            unsigned long long a2[8] = {a01.x, a01.y, a23.x, a23.y,
                                        a45.x, a45.y, a67.x, a67.y};
            unsigned long long b2[4] = {b01.x, b01.y, b23.x, b23.y};
#pragma unroll
            for (int i = 0; i < 8; i++)
#pragma unroll
                for (int j = 0; j < 4; j++)
                    ffma2(acc[i][j], a2[i], b2[j]);
        }
    }

#pragma unroll
    for (int i = 0; i < 8; i++) {
        int mrow = ty * 8 + i;
        int m = m0 + mrow;
        if (m >= ne) break;
        const int token = stok[mrow];
        const float p   = sp[mrow];
        float* op = out + (size_t)token * C_DIM + n0 + tx * 8;
#pragma unroll
        for (int j = 0; j < 4; j++) {
            atomicAdd(op + 2 * j + 0, p * lo32(acc[i][j]));
            atomicAdd(op + 2 * j + 1, p * hi32(acc[i][j]));
        }
    }
}

// ---------------- host launch ----------------
extern "C" void kernel_launch(void* const* d_in, const int* in_sizes, int n_in,
                              void* d_out, int out_size) {
    const float* x  = (const float*)d_in[0];
    const float* rw = (const float*)d_in[1];
    const float* w1 = (const float*)d_in[2];
    const float* w2 = (const float*)d_in[3];
    float* out = (float*)d_out;

    cudaMemsetAsync(out, 0, (size_t)out_size * sizeof(float));
    init_kernel<<<1, 32>>>();
    router_kernel<<<N_TOK / 8, 256>>>(x, rw);
    offsets_kernel<<<1, 1>>>();
    scatter_kernel<<<N_TOK / 256, 256>>>();

    dim3 g1(D_DIM / BN, 64, E_NUM);
    gemm1_kernel<<<g1, 256>>>(x, w1);
    dim3 g2(C_DIM / BN, 64, E_NUM);
    gemm2_kernel<<<g2, 256>>>(w2, out);
}

// round 14
// speedup vs baseline: 3.2691x; 3.2691x over previous
#include <cuda_runtime.h>
#include <cuda_bf16.h>
#include <math.h>
#include <stdint.h>

#define N_TOK 8192
#define C_DIM 1024
#define D_DIM 1024
#define E_NUM 8
#define SLOTS (N_TOK * 2)

#define BM 128
#define BN 128
#define BK 16
#define KTOT 1024
#define NCHUNK (KTOT / BK)   // 64

#define ASTR 24    // A smem row stride in bf16 (48B)
#define BSTR 136   // B smem row stride in bf16 (272B)

// ---------------- device scratch (NEVER passed as kernel args from host) ----------------
__device__ int   g_counts[E_NUM];
__device__ int   g_base[E_NUM];
__device__ int   g_cursor[E_NUM];
__device__ int   g_tok_e[SLOTS];
__device__ float g_tok_p[SLOTS];
__device__ int   g_slot_tok[SLOTS];
__device__ float g_slot_p[SLOTS];

__device__ __nv_bfloat16 g_xh[(size_t)N_TOK * C_DIM];
__device__ __nv_bfloat16 g_xl[(size_t)N_TOK * C_DIM];
__device__ __nv_bfloat16 g_w1h[(size_t)E_NUM * C_DIM * D_DIM];
__device__ __nv_bfloat16 g_w1l[(size_t)E_NUM * C_DIM * D_DIM];
__device__ __nv_bfloat16 g_w2h[(size_t)E_NUM * D_DIM * C_DIM];
__device__ __nv_bfloat16 g_w2l[(size_t)E_NUM * D_DIM * C_DIM];
__device__ __nv_bfloat16 g_hh[(size_t)(SLOTS + BM) * D_DIM];
__device__ __nv_bfloat16 g_hl[(size_t)(SLOTS + BM) * D_DIM];

// ---------------- helpers ----------------
__device__ __forceinline__ void mma_bf16(float* d, const uint32_t* a, const uint32_t* b) {
    asm volatile(
        "mma.sync.aligned.m16n8k16.row.col.f32.bf16.bf16.f32 "
        "{%0,%1,%2,%3}, {%4,%5,%6,%7}, {%8,%9}, {%0,%1,%2,%3};"
        : "+f"(d[0]), "+f"(d[1]), "+f"(d[2]), "+f"(d[3])
        : "r"(a[0]), "r"(a[1]), "r"(a[2]), "r"(a[3]), "r"(b[0]), "r"(b[1]));
}
__device__ __forceinline__ void ldsm_x4(uint32_t* r, uint32_t addr) {
    asm volatile("ldmatrix.sync.aligned.m8n8.x4.shared.b16 {%0,%1,%2,%3}, [%4];"
                 : "=r"(r[0]), "=r"(r[1]), "=r"(r[2]), "=r"(r[3]) : "r"(addr));
}
__device__ __forceinline__ void ldsm_x2t(uint32_t* r, uint32_t addr) {
    asm volatile("ldmatrix.sync.aligned.m8n8.x2.trans.shared.b16 {%0,%1}, [%2];"
                 : "=r"(r[0]), "=r"(r[1]) : "r"(addr));
}
__device__ __forceinline__ void split2(float v, __nv_bfloat16& h, __nv_bfloat16& l) {
    h = __float2bfloat16_rn(v);
    l = __float2bfloat16_rn(v - __bfloat162float(h));
}

// ---------------- small kernels (proven) ----------------
__global__ void init_kernel() {
    int t = threadIdx.x;
    if (t < E_NUM) g_counts[t] = 0;
}

__global__ void router_kernel(const float* __restrict__ x,
                              const float* __restrict__ rw) {
    __shared__ float srw[E_NUM * C_DIM];
    int tid = threadIdx.x;
    for (int i = tid; i < E_NUM * C_DIM; i += 256) srw[i] = rw[i];
    __syncthreads();

    int warp = tid >> 5, lane = tid & 31;
    int token = blockIdx.x * 8 + warp;
    const float* xr = x + (size_t)token * C_DIM;

    float acc[E_NUM];
#pragma unroll
    for (int e = 0; e < E_NUM; e++) acc[e] = 0.f;
    for (int c = lane; c < C_DIM; c += 32) {
        float xv = xr[c];
#pragma unroll
        for (int e = 0; e < E_NUM; e++) acc[e] += xv * srw[e * C_DIM + c];
    }
#pragma unroll
    for (int e = 0; e < E_NUM; e++) {
#pragma unroll
        for (int o = 16; o; o >>= 1)
            acc[e] += __shfl_xor_sync(0xffffffffu, acc[e], o);
    }
    if (lane == 0) {
        int e0 = 0; float v0 = acc[0];
#pragma unroll
        for (int e = 1; e < E_NUM; e++)
            if (acc[e] > v0) { v0 = acc[e]; e0 = e; }
        int e1 = -1; float v1 = -INFINITY;
#pragma unroll
        for (int e = 0; e < E_NUM; e++)
            if (e != e0 && acc[e] > v1) { v1 = acc[e]; e1 = e; }
        float t  = expf(v1 - v0);
        float p0 = 1.f / (1.f + t);
        float p1 = t / (1.f + t);
        g_tok_e[token * 2 + 0] = e0;
        g_tok_e[token * 2 + 1] = e1;
        g_tok_p[token * 2 + 0] = p0;
        g_tok_p[token * 2 + 1] = p1;
        atomicAdd(&g_counts[e0], 1);
        atomicAdd(&g_counts[e1], 1);
    }
}

__global__ void offsets_kernel() {
    int s = 0;
    for (int e = 0; e < E_NUM; e++) {
        g_base[e]   = s;
        g_cursor[e] = s;
        s += g_counts[e];
    }
}

__global__ void scatter_kernel() {
    int n = blockIdx.x * blockDim.x + threadIdx.x;
    if (n >= N_TOK) return;
#pragma unroll
    for (int k = 0; k < 2; k++) {
        int e = g_tok_e[n * 2 + k];
        int slot = atomicAdd(&g_cursor[e], 1);
        g_slot_tok[slot] = n;
        g_slot_p[slot]   = g_tok_p[n * 2 + k];
    }
}

// ---- splits: device symbols referenced DIRECTLY (the fix) ----
__device__ __forceinline__ void split_store(const float* __restrict__ src,
                                            __nv_bfloat16* dh, __nv_bfloat16* dl,
                                            size_t i) {
    float4 v = *(const float4*)(src + i);
    __nv_bfloat16 h0, l0, h1, l1, h2, l2, h3, l3;
    split2(v.x, h0, l0); split2(v.y, h1, l1);
    split2(v.z, h2, l2); split2(v.w, h3, l3);
    __nv_bfloat162* ph = (__nv_bfloat162*)(dh + i);
    __nv_bfloat162* pl = (__nv_bfloat162*)(dl + i);
    ph[0] = __nv_bfloat162(h0, h1); ph[1] = __nv_bfloat162(h2, h3);
    pl[0] = __nv_bfloat162(l0, l1); pl[1] = __nv_bfloat162(l2, l3);
}

__global__ void split_x_kernel(const float* __restrict__ x) {
    size_t i = (size_t)(blockIdx.x * 256 + threadIdx.x) * 4;
    split_store(x, g_xh, g_xl, i);
}
__global__ void split_w1_kernel(const float* __restrict__ w1) {
    size_t i = (size_t)(blockIdx.x * 256 + threadIdx.x) * 4;
    split_store(w1, g_w1h, g_w1l, i);
}
__global__ void split_w2_kernel(const float* __restrict__ w2) {
    size_t i = (size_t)(blockIdx.x * 256 + threadIdx.x) * 4;
    split_store(w2, g_w2h, g_w2l, i);
}

// ---------------- GEMM1: H = relu(x[tok] @ w1[e])^2, bf16-split MMA ----------------
__global__ void __launch_bounds__(256)
gemm1_kernel() {
    const int e  = blockIdx.z;
    const int ne = g_counts[e];
    const int m0 = blockIdx.y * BM;
    if (m0 >= ne) return;
    const int base = g_base[e];
    const int n0   = blockIdx.x * BN;

    __shared__ __align__(16) __nv_bfloat16 sAh[BM][ASTR];
    __shared__ __align__(16) __nv_bfloat16 sAl[BM][ASTR];
    __shared__ __align__(16) __nv_bfloat16 sBh[BK][BSTR];
    __shared__ __align__(16) __nv_bfloat16 sBl[BK][BSTR];
    __shared__ int stok[BM];

    const int t = threadIdx.x;
    const int wid = t >> 5, lane = t & 31;
    const int g = lane >> 2, tg = lane & 3;

    if (t < BM) {
        int m = m0 + t;
        stok[t] = (m < ne) ? g_slot_tok[base + m] : 0;
    }
    __syncthreads();

    const int ar = t >> 1, ah = (t & 1) * 8;
    const int br = t >> 4, bc = (t & 15) * 8;

    const size_t arow = (size_t)stok[ar];
    const __nv_bfloat16* agh = g_xh + arow * KTOT + ah;
    const __nv_bfloat16* agl = g_xl + arow * KTOT + ah;
    const __nv_bfloat16* bgh = g_w1h + ((size_t)e << 20) + (size_t)br * KTOT + n0 + bc;
    const __nv_bfloat16* bgl = g_w1l + ((size_t)e << 20) + (size_t)br * KTOT + n0 + bc;

    const int wm = (wid >> 2) * 64;
    const int wn = (wid & 3) * 32;

    const int lr = lane & 15;
    const int lc = (lane >> 4) * 8;
    uint32_t aAh[4], aAl[4];
#pragma unroll
    for (int mt = 0; mt < 4; mt++) {
        aAh[mt] = (uint32_t)__cvta_generic_to_shared(&sAh[wm + mt * 16 + lr][lc]);
        aAl[mt] = (uint32_t)__cvta_generic_to_shared(&sAl[wm + mt * 16 + lr][lc]);
    }
    uint32_t aBh[4], aBl[4];
#pragma unroll
    for (int nt = 0; nt < 4; nt++) {
        aBh[nt] = (uint32_t)__cvta_generic_to_shared(&sBh[lr][wn + nt * 8]);
        aBl[nt] = (uint32_t)__cvta_generic_to_shared(&sBl[lr][wn + nt * 8]);
    }

    float acc[4][4][4];
#pragma unroll
    for (int i = 0; i < 4; i++)
#pragma unroll
        for (int j = 0; j < 4; j++)
#pragma unroll
            for (int q = 0; q < 4; q++) acc[i][j][q] = 0.f;

    uint4 pah = *(const uint4*)(agh);
    uint4 pal = *(const uint4*)(agl);
    uint4 pbh = *(const uint4*)(bgh);
    uint4 pbl = *(const uint4*)(bgl);

    for (int c = 0; c < NCHUNK; c++) {
        __syncthreads();
        *(uint4*)&sAh[ar][ah] = pah;
        *(uint4*)&sAl[ar][ah] = pal;
        *(uint4*)&sBh[br][bc] = pbh;
        *(uint4*)&sBl[br][bc] = pbl;
        __syncthreads();

        if (c + 1 < NCHUNK) {
            pah = *(const uint4*)(agh + (c + 1) * BK);
            pal = *(const uint4*)(agl + (c + 1) * BK);
            pbh = *(const uint4*)(bgh + (size_t)(c + 1) * BK * KTOT);
            pbl = *(const uint4*)(bgl + (size_t)(c + 1) * BK * KTOT);
        }

        uint32_t fah[4][4], fal[4][4];
#pragma unroll
        for (int mt = 0; mt < 4; mt++) {
            ldsm_x4(fah[mt], aAh[mt]);
            ldsm_x4(fal[mt], aAl[mt]);
        }
        uint32_t fbh[4][2], fbl[4][2];
#pragma unroll
        for (int nt = 0; nt < 4; nt++) {
            ldsm_x2t(fbh[nt], aBh[nt]);
            ldsm_x2t(fbl[nt], aBl[nt]);
        }
#pragma unroll
        for (int mt = 0; mt < 4; mt++)
#pragma unroll
            for (int nt = 0; nt < 4; nt++) {
                mma_bf16(acc[mt][nt], fah[mt], fbh[nt]);
                mma_bf16(acc[mt][nt], fah[mt], fbl[nt]);
                mma_bf16(acc[mt][nt], fal[mt], fbh[nt]);
            }
    }

#pragma unroll
    for (int mt = 0; mt < 4; mt++) {
#pragma unroll
        for (int half = 0; half < 2; half++) {
            const int mrow = wm + mt * 16 + g + half * 8;
            if (m0 + mrow < ne) {
                size_t roff = (size_t)(base + m0 + mrow) * KTOT + n0 + wn + tg * 2;
#pragma unroll
                for (int nt = 0; nt < 4; nt++) {
                    float q0 = fmaxf(acc[mt][nt][half * 2 + 0], 0.f);
                    float q1 = fmaxf(acc[mt][nt][half * 2 + 1], 0.f);
                    float h0 = q0 * q0, h1 = q1 * q1;
                    __nv_bfloat16 a0, b0, a1, b1;
                    split2(h0, a0, b0);
                    split2(h1, a1, b1);
                    *(__nv_bfloat162*)(g_hh + roff + nt * 8) = __nv_bfloat162(a0, a1);
                    *(__nv_bfloat162*)(g_hl + roff + nt * 8) = __nv_bfloat162(b0, b1);
                }
            }
        }
    }
}

// ---------------- GEMM2: out[tok] += p * (H @ w2[e]), bf16-split MMA ----------------
__global__ void __launch_bounds__(256)
gemm2_kernel(float* __restrict__ out) {
    const int e  = blockIdx.z;
    const int ne = g_counts[e];
    const int m0 = blockIdx.y * BM;
    if (m0 >= ne) return;
    const int base = g_base[e];
    const int n0   = blockIdx.x * BN;

    __shared__ __align__(16) __nv_bfloat16 sAh[BM][ASTR];
    __shared__ __align__(16) __nv_bfloat16 sAl[BM][ASTR];
    __shared__ __align__(16) __nv_bfloat16 sBh[BK][BSTR];
    __shared__ __align__(16) __nv_bfloat16 sBl[BK][BSTR];
    __shared__ int   stok[BM];
    __shared__ float sp[BM];

    const int t = threadIdx.x;
    const int wid = t >> 5, lane = t & 31;
    const int g = lane >> 2, tg = lane & 3;

    if (t < BM) {
        int m = m0 + t;
        if (m < ne) {
            stok[t] = g_slot_tok[base + m];
            sp[t]   = g_slot_p[base + m];
        } else {
            stok[t] = 0;
            sp[t]   = 0.f;
        }
    }
    __syncthreads();

    const int ar = t >> 1, ah = (t & 1) * 8;
    const int br = t >> 4, bc = (t & 15) * 8;

    const size_t arow = (size_t)(base + m0 + ar);
    const __nv_bfloat16* agh = g_hh + arow * KTOT + ah;
    const __nv_bfloat16* agl = g_hl + arow * KTOT + ah;
    const __nv_bfloat16* bgh = g_w2h + ((size_t)e << 20) + (size_t)br * KTOT + n0 + bc;
    const __nv_bfloat16* bgl = g_w2l + ((size_t)e << 20) + (size_t)br * KTOT + n0 + bc;

    const int wm = (wid >> 2) * 64;
    const int wn = (wid & 3) * 32;

    const int lr = lane & 15;
    const int lc = (lane >> 4) * 8;
    uint32_t aAh[4], aAl[4];
#pragma unroll
    for (int mt = 0; mt < 4; mt++) {
        aAh[mt] = (uint32_t)__cvta_generic_to_shared(&sAh[wm + mt * 16 + lr][lc]);
        aAl[mt] = (uint32_t)__cvta_generic_to_shared(&sAl[wm + mt * 16 + lr][lc]);
    }
    uint32_t aBh[4], aBl[4];
#pragma unroll
    for (int nt = 0; nt < 4; nt++) {
        aBh[nt] = (uint32_t)__cvta_generic_to_shared(&sBh[lr][wn + nt * 8]);
        aBl[nt] = (uint32_t)__cvta_generic_to_shared(&sBl[lr][wn + nt * 8]);
    }

    float acc[4][4][4];
#pragma unroll
    for (int i = 0; i < 4; i++)
#pragma unroll
        for (int j = 0; j < 4; j++)
#pragma unroll
            for (int q = 0; q < 4; q++) acc[i][j][q] = 0.f;

    uint4 pah = *(const uint4*)(agh);
    uint4 pal = *(const uint4*)(agl);
    uint4 pbh = *(const uint4*)(bgh);
    uint4 pbl = *(const uint4*)(bgl);

    for (int c = 0; c < NCHUNK; c++) {
        __syncthreads();
        *(uint4*)&sAh[ar][ah] = pah;
        *(uint4*)&sAl[ar][ah] = pal;
        *(uint4*)&sBh[br][bc] = pbh;
        *(uint4*)&sBl[br][bc] = pbl;
        __syncthreads();

        if (c + 1 < NCHUNK) {
            pah = *(const uint4*)(agh + (c + 1) * BK);
            pal = *(const uint4*)(agl + (c + 1) * BK);
            pbh = *(const uint4*)(bgh + (size_t)(c + 1) * BK * KTOT);
            pbl = *(const uint4*)(bgl + (size_t)(c + 1) * BK * KTOT);
        }

        uint32_t fah[4][4], fal[4][4];
#pragma unroll
        for (int mt = 0; mt < 4; mt++) {
            ldsm_x4(fah[mt], aAh[mt]);
            ldsm_x4(fal[mt], aAl[mt]);
        }
        uint32_t fbh[4][2], fbl[4][2];
#pragma unroll
        for (int nt = 0; nt < 4; nt++) {
            ldsm_x2t(fbh[nt], aBh[nt]);
            ldsm_x2t(fbl[nt], aBl[nt]);
        }
#pragma unroll
        for (int mt = 0; mt < 4; mt++)
#pragma unroll
            for (int nt = 0; nt < 4; nt++) {
                mma_bf16(acc[mt][nt], fah[mt], fbh[nt]);
                mma_bf16(acc[mt][nt], fah[mt], fbl[nt]);
                mma_bf16(acc[mt][nt], fal[mt], fbh[nt]);
            }
    }

#pragma unroll
    for (int mt = 0; mt < 4; mt++) {
#pragma unroll
        for (int half = 0; half < 2; half++) {
            const int mrow = wm + mt * 16 + g + half * 8;
            if (m0 + mrow < ne) {
                const int token = stok[mrow];
                const float p   = sp[mrow];
                float* op = out + (size_t)token * C_DIM + n0 + wn + tg * 2;
#pragma unroll
                for (int nt = 0; nt < 4; nt++) {
                    atomicAdd(op + nt * 8 + 0, p * acc[mt][nt][half * 2 + 0]);
                    atomicAdd(op + nt * 8 + 1, p * acc[mt][nt][half * 2 + 1]);
                }
            }
        }
    }
}

// ---------------- host launch ----------------
extern "C" void kernel_launch(void* const* d_in, const int* in_sizes, int n_in,
                              void* d_out, int out_size) {
    const float* x  = (const float*)d_in[0];
    const float* rw = (const float*)d_in[1];
    const float* w1 = (const float*)d_in[2];
    const float* w2 = (const float*)d_in[3];
    float* out = (float*)d_out;

    cudaMemsetAsync(out, 0, (size_t)out_size * sizeof(float));
    init_kernel<<<1, 32>>>();
    router_kernel<<<N_TOK / 8, 256>>>(x, rw);
    offsets_kernel<<<1, 1>>>();
    scatter_kernel<<<N_TOK / 256, 256>>>();

    split_x_kernel<<<(N_TOK * C_DIM / 4) / 256, 256>>>(x);
    split_w1_kernel<<<(E_NUM * C_DIM * D_DIM / 4) / 256, 256>>>(w1);
    split_w2_kernel<<<(E_NUM * D_DIM * C_DIM / 4) / 256, 256>>>(w2);

    dim3 g1(D_DIM / BN, 64, E_NUM);
    gemm1_kernel<<<g1, 256>>>();
    dim3 g2(C_DIM / BN, 64, E_NUM);
    gemm2_kernel<<<g2, 256>>>(out);
}

// round 16
// speedup vs baseline: 3.8775x; 1.1861x over previous
#include <cuda_runtime.h>
#include <cuda_bf16.h>
#include <math.h>
#include <stdint.h>

#define N_TOK 8192
#define C_DIM 1024
#define D_DIM 1024
#define E_NUM 8
#define SLOTS (N_TOK * 2)

#define BM 128
#define BN 128
#define BK 16
#define KTOT 1024
#define NCHUNK (KTOT / BK)   // 64

#define ASTR 24    // A smem row stride in bf16 (48B)
#define BSTR 136   // B smem row stride in bf16 (272B)
#define A_STAGE_B (BM * ASTR * 2)   // 6144 bytes per A stage
#define B_STAGE_B (BK * BSTR * 2)   // 4352 bytes per B stage

// ---------------- device scratch (NEVER passed as kernel args from host) ----------------
__device__ int   g_counts[E_NUM];
__device__ int   g_base[E_NUM];
__device__ int   g_cursor[E_NUM];
__device__ int   g_tok_e[SLOTS];
__device__ float g_tok_p[SLOTS];
__device__ int   g_slot_tok[SLOTS];
__device__ float g_slot_p[SLOTS];

__device__ __nv_bfloat16 g_xh[(size_t)N_TOK * C_DIM];
__device__ __nv_bfloat16 g_xl[(size_t)N_TOK * C_DIM];
__device__ __nv_bfloat16 g_w1h[(size_t)E_NUM * C_DIM * D_DIM];
__device__ __nv_bfloat16 g_w1l[(size_t)E_NUM * C_DIM * D_DIM];
__device__ __nv_bfloat16 g_w2h[(size_t)E_NUM * D_DIM * C_DIM];
__device__ __nv_bfloat16 g_w2l[(size_t)E_NUM * D_DIM * C_DIM];
__device__ __nv_bfloat16 g_hh[(size_t)(SLOTS + BM) * D_DIM];
__device__ __nv_bfloat16 g_hl[(size_t)(SLOTS + BM) * D_DIM];

// ---------------- helpers ----------------
__device__ __forceinline__ void mma_bf16(float* d, const uint32_t* a, const uint32_t* b) {
    asm volatile(
        "mma.sync.aligned.m16n8k16.row.col.f32.bf16.bf16.f32 "
        "{%0,%1,%2,%3}, {%4,%5,%6,%7}, {%8,%9}, {%0,%1,%2,%3};"
        : "+f"(d[0]), "+f"(d[1]), "+f"(d[2]), "+f"(d[3])
        : "r"(a[0]), "r"(a[1]), "r"(a[2]), "r"(a[3]), "r"(b[0]), "r"(b[1]));
}
__device__ __forceinline__ void ldsm_x4(uint32_t* r, uint32_t addr) {
    asm volatile("ldmatrix.sync.aligned.m8n8.x4.shared.b16 {%0,%1,%2,%3}, [%4];"
                 : "=r"(r[0]), "=r"(r[1]), "=r"(r[2]), "=r"(r[3]) : "r"(addr));
}
__device__ __forceinline__ void ldsm_x2t(uint32_t* r, uint32_t addr) {
    asm volatile("ldmatrix.sync.aligned.m8n8.x2.trans.shared.b16 {%0,%1}, [%2];"
                 : "=r"(r[0]), "=r"(r[1]) : "r"(addr));
}
__device__ __forceinline__ void split2(float v, __nv_bfloat16& h, __nv_bfloat16& l) {
    h = __float2bfloat16_rn(v);
    l = __float2bfloat16_rn(v - __bfloat162float(h));
}

// ---------------- small kernels (proven) ----------------
__global__ void init_kernel() {
    int t = threadIdx.x;
    if (t < E_NUM) g_counts[t] = 0;
}

__global__ void router_kernel(const float* __restrict__ x,
                              const float* __restrict__ rw) {
    __shared__ float srw[E_NUM * C_DIM];
    int tid = threadIdx.x;
    for (int i = tid; i < E_NUM * C_DIM; i += 256) srw[i] = rw[i];
    __syncthreads();

    int warp = tid >> 5, lane = tid & 31;
    int token = blockIdx.x * 8 + warp;
    const float* xr = x + (size_t)token * C_DIM;

    float acc[E_NUM];
#pragma unroll
    for (int e = 0; e < E_NUM; e++) acc[e] = 0.f;
    for (int c = lane; c < C_DIM; c += 32) {
        float xv = xr[c];
#pragma unroll
        for (int e = 0; e < E_NUM; e++) acc[e] += xv * srw[e * C_DIM + c];
    }
#pragma unroll
    for (int e = 0; e < E_NUM; e++) {
#pragma unroll
        for (int o = 16; o; o >>= 1)
            acc[e] += __shfl_xor_sync(0xffffffffu, acc[e], o);
    }
    if (lane == 0) {
        int e0 = 0; float v0 = acc[0];
#pragma unroll
        for (int e = 1; e < E_NUM; e++)
            if (acc[e] > v0) { v0 = acc[e]; e0 = e; }
        int e1 = -1; float v1 = -INFINITY;
#pragma unroll
        for (int e = 0; e < E_NUM; e++)
            if (e != e0 && acc[e] > v1) { v1 = acc[e]; e1 = e; }
        float t  = expf(v1 - v0);
        float p0 = 1.f / (1.f + t);
        float p1 = t / (1.f + t);
        g_tok_e[token * 2 + 0] = e0;
        g_tok_e[token * 2 + 1] = e1;
        g_tok_p[token * 2 + 0] = p0;
        g_tok_p[token * 2 + 1] = p1;
        atomicAdd(&g_counts[e0], 1);
        atomicAdd(&g_counts[e1], 1);
    }
}

__global__ void offsets_kernel() {
    int s = 0;
    for (int e = 0; e < E_NUM; e++) {
        g_base[e]   = s;
        g_cursor[e] = s;
        s += g_counts[e];
    }
}

__global__ void scatter_kernel() {
    int n = blockIdx.x * blockDim.x + threadIdx.x;
    if (n >= N_TOK) return;
#pragma unroll
    for (int k = 0; k < 2; k++) {
        int e = g_tok_e[n * 2 + k];
        int slot = atomicAdd(&g_cursor[e], 1);
        g_slot_tok[slot] = n;
        g_slot_p[slot]   = g_tok_p[n * 2 + k];
    }
}

// ---- splits: device symbols referenced directly ----
__device__ __forceinline__ void split_store(const float* __restrict__ src,
                                            __nv_bfloat16* dh, __nv_bfloat16* dl,
                                            size_t i) {
    float4 v = *(const float4*)(src + i);
    __nv_bfloat16 h0, l0, h1, l1, h2, l2, h3, l3;
    split2(v.x, h0, l0); split2(v.y, h1, l1);
    split2(v.z, h2, l2); split2(v.w, h3, l3);
    __nv_bfloat162* ph = (__nv_bfloat162*)(dh + i);
    __nv_bfloat162* pl = (__nv_bfloat162*)(dl + i);
    ph[0] = __nv_bfloat162(h0, h1); ph[1] = __nv_bfloat162(h2, h3);
    pl[0] = __nv_bfloat162(l0, l1); pl[1] = __nv_bfloat162(l2, l3);
}

__global__ void split_x_kernel(const float* __restrict__ x) {
    size_t i = (size_t)(blockIdx.x * 256 + threadIdx.x) * 4;
    split_store(x, g_xh, g_xl, i);
}
__global__ void split_w1_kernel(const float* __restrict__ w1) {
    size_t i = (size_t)(blockIdx.x * 256 + threadIdx.x) * 4;
    split_store(w1, g_w1h, g_w1l, i);
}
__global__ void split_w2_kernel(const float* __restrict__ w2) {
    size_t i = (size_t)(blockIdx.x * 256 + threadIdx.x) * 4;
    split_store(w2, g_w2h, g_w2l, i);
}

// ---------------- GEMM1: H = relu(x[tok] @ w1[e])^2 (double-buffered) ----------------
__global__ void __launch_bounds__(256)
gemm1_kernel() {
    const int e  = blockIdx.z;
    const int ne = g_counts[e];
    const int m0 = blockIdx.y * BM;
    if (m0 >= ne) return;
    const int base = g_base[e];
    const int n0   = blockIdx.x * BN;

    __shared__ __align__(16) __nv_bfloat16 sAh[2][BM][ASTR];
    __shared__ __align__(16) __nv_bfloat16 sAl[2][BM][ASTR];
    __shared__ __align__(16) __nv_bfloat16 sBh[2][BK][BSTR];
    __shared__ __align__(16) __nv_bfloat16 sBl[2][BK][BSTR];
    __shared__ int stok[BM];

    const int t = threadIdx.x;
    const int wid = t >> 5, lane = t & 31;
    const int g = lane >> 2, tg = lane & 3;

    if (t < BM) {
        int m = m0 + t;
        stok[t] = (m < ne) ? g_slot_tok[base + m] : 0;
    }
    __syncthreads();

    const int ar = t >> 1, ah = (t & 1) * 8;
    const int br = t >> 4, bc = (t & 15) * 8;

    const size_t arow = (size_t)stok[ar];
    const __nv_bfloat16* agh = g_xh + arow * KTOT + ah;
    const __nv_bfloat16* agl = g_xl + arow * KTOT + ah;
    const __nv_bfloat16* bgh = g_w1h + ((size_t)e << 20) + (size_t)br * KTOT + n0 + bc;
    const __nv_bfloat16* bgl = g_w1l + ((size_t)e << 20) + (size_t)br * KTOT + n0 + bc;

    const int wm = (wid >> 2) * 64;
    const int wn = (wid & 3) * 32;

    const int lr = lane & 15;
    const int lc = (lane >> 4) * 8;
    uint32_t aAh[4], aAl[4];
#pragma unroll
    for (int mt = 0; mt < 4; mt++) {
        aAh[mt] = (uint32_t)__cvta_generic_to_shared(&sAh[0][wm + mt * 16 + lr][lc]);
        aAl[mt] = (uint32_t)__cvta_generic_to_shared(&sAl[0][wm + mt * 16 + lr][lc]);
    }
    uint32_t aBh[4], aBl[4];
#pragma unroll
    for (int nt = 0; nt < 4; nt++) {
        aBh[nt] = (uint32_t)__cvta_generic_to_shared(&sBh[0][lr][wn + nt * 8]);
        aBl[nt] = (uint32_t)__cvta_generic_to_shared(&sBl[0][lr][wn + nt * 8]);
    }

    float acc[4][4][4];
#pragma unroll
    for (int i = 0; i < 4; i++)
#pragma unroll
        for (int j = 0; j < 4; j++)
#pragma unroll
            for (int q = 0; q < 4; q++) acc[i][j][q] = 0.f;

    // chunk 0 -> buffer 0
    {
        uint4 pah = *(const uint4*)(agh);
        uint4 pal = *(const uint4*)(agl);
        uint4 pbh = *(const uint4*)(bgh);
        uint4 pbl = *(const uint4*)(bgl);
        *(uint4*)&sAh[0][ar][ah] = pah;
        *(uint4*)&sAl[0][ar][ah] = pal;
        *(uint4*)&sBh[0][br][bc] = pbh;
        *(uint4*)&sBl[0][br][bc] = pbl;
    }
    __syncthreads();

    for (int c = 0; c < NCHUNK; c++) {
        const int cur = c & 1, nxt = cur ^ 1;
        uint4 pah, pal, pbh, pbl;
        if (c + 1 < NCHUNK) {  // issue global loads early; they complete under the MMAs
            pah = *(const uint4*)(agh + (c + 1) * BK);
            pal = *(const uint4*)(agl + (c + 1) * BK);
            pbh = *(const uint4*)(bgh + (size_t)(c + 1) * BK * KTOT);
            pbl = *(const uint4*)(bgl + (size_t)(c + 1) * BK * KTOT);
        }

        const uint32_t ao = cur * A_STAGE_B;
        const uint32_t bo = cur * B_STAGE_B;
        uint32_t fah[4][4], fal[4][4];
#pragma unroll
        for (int mt = 0; mt < 4; mt++) {
            ldsm_x4(fah[mt], aAh[mt] + ao);
            ldsm_x4(fal[mt], aAl[mt] + ao);
        }
        uint32_t fbh[4][2], fbl[4][2];
#pragma unroll
        for (int nt = 0; nt < 4; nt++) {
            ldsm_x2t(fbh[nt], aBh[nt] + bo);
            ldsm_x2t(fbl[nt], aBl[nt] + bo);
        }
#pragma unroll
        for (int mt = 0; mt < 4; mt++)
#pragma unroll
            for (int nt = 0; nt < 4; nt++) {
                mma_bf16(acc[mt][nt], fah[mt], fbh[nt]);
                mma_bf16(acc[mt][nt], fah[mt], fbl[nt]);
                mma_bf16(acc[mt][nt], fal[mt], fbh[nt]);
            }

        if (c + 1 < NCHUNK) {
            *(uint4*)&sAh[nxt][ar][ah] = pah;
            *(uint4*)&sAl[nxt][ar][ah] = pal;
            *(uint4*)&sBh[nxt][br][bc] = pbh;
            *(uint4*)&sBl[nxt][br][bc] = pbl;
            __syncthreads();
        }
    }

#pragma unroll
    for (int mt = 0; mt < 4; mt++) {
#pragma unroll
        for (int half = 0; half < 2; half++) {
            const int mrow = wm + mt * 16 + g + half * 8;
            if (m0 + mrow < ne) {
                size_t roff = (size_t)(base + m0 + mrow) * KTOT + n0 + wn + tg * 2;
#pragma unroll
                for (int nt = 0; nt < 4; nt++) {
                    float q0 = fmaxf(acc[mt][nt][half * 2 + 0], 0.f);
                    float q1 = fmaxf(acc[mt][nt][half * 2 + 1], 0.f);
                    float h0 = q0 * q0, h1 = q1 * q1;
                    __nv_bfloat16 a0, b0, a1, b1;
                    split2(h0, a0, b0);
                    split2(h1, a1, b1);
                    *(__nv_bfloat162*)(g_hh + roff + nt * 8) = __nv_bfloat162(a0, a1);
                    *(__nv_bfloat162*)(g_hl + roff + nt * 8) = __nv_bfloat162(b0, b1);
                }
            }
        }
    }
}

// ---------------- GEMM2: out[tok] += p * (H @ w2[e]) (double-buffered) ----------------
__global__ void __launch_bounds__(256)
gemm2_kernel(float* __restrict__ out) {
    const int e  = blockIdx.z;
    const int ne = g_counts[e];
    const int m0 = blockIdx.y * BM;
    if (m0 >= ne) return;
    const int base = g_base[e];
    const int n0   = blockIdx.x * BN;

    __shared__ __align__(16) __nv_bfloat16 sAh[2][BM][ASTR];
    __shared__ __align__(16) __nv_bfloat16 sAl[2][BM][ASTR];
    __shared__ __align__(16) __nv_bfloat16 sBh[2][BK][BSTR];
    __shared__ __align__(16) __nv_bfloat16 sBl[2][BK][BSTR];
    __shared__ int   stok[BM];
    __shared__ float sp[BM];

    const int t = threadIdx.x;
    const int wid = t >> 5, lane = t & 31;
    const int g = lane >> 2, tg = lane & 3;

    if (t < BM) {
        int m = m0 + t;
        if (m < ne) {
            stok[t] = g_slot_tok[base + m];
            sp[t]   = g_slot_p[base + m];
        } else {
            stok[t] = 0;
            sp[t]   = 0.f;
        }
    }
    __syncthreads();

    const int ar = t >> 1, ah = (t & 1) * 8;
    const int br = t >> 4, bc = (t & 15) * 8;

    const size_t arow = (size_t)(base + m0 + ar);
    const __nv_bfloat16* agh = g_hh + arow * KTOT + ah;
    const __nv_bfloat16* agl = g_hl + arow * KTOT + ah;
    const __nv_bfloat16* bgh = g_w2h + ((size_t)e << 20) + (size_t)br * KTOT + n0 + bc;
    const __nv_bfloat16* bgl = g_w2l + ((size_t)e << 20) + (size_t)br * KTOT + n0 + bc;

    const int wm = (wid >> 2) * 64;
    const int wn = (wid & 3) * 32;

    const int lr = lane & 15;
    const int lc = (lane >> 4) * 8;
    uint32_t aAh[4], aAl[4];
#pragma unroll
    for (int mt = 0; mt < 4; mt++) {
        aAh[mt] = (uint32_t)__cvta_generic_to_shared(&sAh[0][wm + mt * 16 + lr][lc]);
        aAl[mt] = (uint32_t)__cvta_generic_to_shared(&sAl[0][wm + mt * 16 + lr][lc]);
    }
    uint32_t aBh[4], aBl[4];
#pragma unroll
    for (int nt = 0; nt < 4; nt++) {
        aBh[nt] = (uint32_t)__cvta_generic_to_shared(&sBh[0][lr][wn + nt * 8]);
        aBl[nt] = (uint32_t)__cvta_generic_to_shared(&sBl[0][lr][wn + nt * 8]);
    }

    float acc[4][4][4];
#pragma unroll
    for (int i = 0; i < 4; i++)
#pragma unroll
        for (int j = 0; j < 4; j++)
#pragma unroll
            for (int q = 0; q < 4; q++) acc[i][j][q] = 0.f;

    {
        uint4 pah = *(const uint4*)(agh);
        uint4 pal = *(const uint4*)(agl);
        uint4 pbh = *(const uint4*)(bgh);
        uint4 pbl = *(const uint4*)(bgl);
        *(uint4*)&sAh[0][ar][ah] = pah;
        *(uint4*)&sAl[0][ar][ah] = pal;
        *(uint4*)&sBh[0][br][bc] = pbh;
        *(uint4*)&sBl[0][br][bc] = pbl;
    }
    __syncthreads();

    for (int c = 0; c < NCHUNK; c++) {
        const int cur = c & 1, nxt = cur ^ 1;
        uint4 pah, pal, pbh, pbl;
        if (c + 1 < NCHUNK) {
            pah = *(const uint4*)(agh + (c + 1) * BK);
            pal = *(const uint4*)(agl + (c + 1) * BK);
            pbh = *(const uint4*)(bgh + (size_t)(c + 1) * BK * KTOT);
            pbl = *(const uint4*)(bgl + (size_t)(c + 1) * BK * KTOT);
        }

        const uint32_t ao = cur * A_STAGE_B;
        const uint32_t bo = cur * B_STAGE_B;
        uint32_t fah[4][4], fal[4][4];
#pragma unroll
        for (int mt = 0; mt < 4; mt++) {
            ldsm_x4(fah[mt], aAh[mt] + ao);
            ldsm_x4(fal[mt], aAl[mt] + ao);
        }
        uint32_t fbh[4][2], fbl[4][2];
#pragma unroll
        for (int nt = 0; nt < 4; nt++) {
            ldsm_x2t(fbh[nt], aBh[nt] + bo);
            ldsm_x2t(fbl[nt], aBl[nt] + bo);
        }
#pragma unroll
        for (int mt = 0; mt < 4; mt++)
#pragma unroll
            for (int nt = 0; nt < 4; nt++) {
                mma_bf16(acc[mt][nt], fah[mt], fbh[nt]);
                mma_bf16(acc[mt][nt], fah[mt], fbl[nt]);
                mma_bf16(acc[mt][nt], fal[mt], fbh[nt]);
            }

        if (c + 1 < NCHUNK) {
            *(uint4*)&sAh[nxt][ar][ah] = pah;
            *(uint4*)&sAl[nxt][ar][ah] = pal;
            *(uint4*)&sBh[nxt][br][bc] = pbh;
            *(uint4*)&sBl[nxt][br][bc] = pbl;
            __syncthreads();
        }
    }

#pragma unroll
    for (int mt = 0; mt < 4; mt++) {
#pragma unroll
        for (int half = 0; half < 2; half++) {
            const int mrow = wm + mt * 16 + g + half * 8;
            if (m0 + mrow < ne) {
                const int token = stok[mrow];
                const float p   = sp[mrow];
                float* op = out + (size_t)token * C_DIM + n0 + wn + tg * 2;
#pragma unroll
                for (int nt = 0; nt < 4; nt++) {
                    atomicAdd(op + nt * 8 + 0, p * acc[mt][nt][half * 2 + 0]);
                    atomicAdd(op + nt * 8 + 1, p * acc[mt][nt][half * 2 + 1]);
                }
            }
        }
    }
}

// ---------------- host launch ----------------
extern "C" void kernel_launch(void* const* d_in, const int* in_sizes, int n_in,
                              void* d_out, int out_size) {
    const float* x  = (const float*)d_in[0];
    const float* rw = (const float*)d_in[1];
    const float* w1 = (const float*)d_in[2];
    const float* w2 = (const float*)d_in[3];
    float* out = (float*)d_out;

    cudaMemsetAsync(out, 0, (size_t)out_size * sizeof(float));
    init_kernel<<<1, 32>>>();
    router_kernel<<<N_TOK / 8, 256>>>(x, rw);
    offsets_kernel<<<1, 1>>>();
    scatter_kernel<<<N_TOK / 256, 256>>>();

    split_x_kernel<<<(N_TOK * C_DIM / 4) / 256, 256>>>(x);
    split_w1_kernel<<<(E_NUM * C_DIM * D_DIM / 4) / 256, 256>>>(w1);
    split_w2_kernel<<<(E_NUM * D_DIM * C_DIM / 4) / 256, 256>>>(w2);

    dim3 g1(D_DIM / BN, 64, E_NUM);
    gemm1_kernel<<<g1, 256>>>();
    dim3 g2(C_DIM / BN, 64, E_NUM);
    gemm2_kernel<<<g2, 256>>>(out);
}